// round 14
// baseline (speedup 1.0000x reference)
#include <cuda_runtime.h>
#include <cuda_fp16.h>
#include <cstdint>

namespace {
constexpr int kB  = 1024;
constexpr int kL  = 26;
constexpr int kA  = 8192;
constexpr int kC1 = 256;
constexpr int kD  = 512;
constexpr int kE  = 1024;
constexpr int kM  = kB * kL;      // 26624
constexpr float kThr = 1e-6f;
constexpr int LDH   = 40;         // fp16 gemm smem row stride (halves): BK=32 + 8
constexpr int WS_LDH = 520;       // GRU resident w_hh stride (halves)
constexpr int HT_LDH = 40;        // GRU h-tile stride (halves)
constexpr int kChunks = 4;
constexpr int kRowsPerChunk = kM / kChunks;       // 6656
constexpr int kTilesPerChunk = kRowsPerChunk / 128; // 52
}

// ---------------- scratch (allocation-free) ----------------
__device__ __half g_xh[(size_t)kM * kA];        // x in fp16
__device__ __half g_h1[(size_t)kM * kC1];
__device__ __half g_h2[(size_t)kM * kD];
__device__ __half g_gi[(size_t)kM * 3 * kD];
__device__ __half g_hA[(size_t)kB * kD];
__device__ __half g_hB[(size_t)kB * kD];
__device__ __half g_rw1h[(size_t)kC1 * kA];
__device__ __half g_rw2h[(size_t)kD * kC1];
__device__ __half g_rwihh[(size_t)3 * kD * kD];
__device__ __half g_rlinh[(size_t)kE * kD];
__device__ unsigned g_bar_count = 0;
__device__ unsigned g_bar_gen   = 0;

// ---------------- helpers ----------------
__device__ __forceinline__ void mma_f16(float d[4], const uint32_t a[4], uint32_t b0, uint32_t b1) {
    asm volatile(
        "mma.sync.aligned.m16n8k16.row.col.f32.f16.f16.f32 "
        "{%0,%1,%2,%3}, {%4,%5,%6,%7}, {%8,%9}, {%0,%1,%2,%3};"
        : "+f"(d[0]), "+f"(d[1]), "+f"(d[2]), "+f"(d[3])
        : "r"(a[0]), "r"(a[1]), "r"(a[2]), "r"(a[3]), "r"(b0), "r"(b1));
}
__device__ __forceinline__ void cp16(uint32_t saddr, const void* g) {
    asm volatile("cp.async.cg.shared.global [%0], [%1], 16;\n" :: "r"(saddr), "l"(g));
}
__device__ __forceinline__ uint32_t smem_u32(const void* p) {
    uint32_t a;
    asm("{ .reg .u64 t; cvta.to.shared.u64 t, %1; cvt.u32.u64 %0, t; }" : "=r"(a) : "l"(p));
    return a;
}
__device__ __forceinline__ void ldsm4(uint32_t r[4], uint32_t saddr) {
    asm volatile("ldmatrix.sync.aligned.m8n8.x4.shared.b16 {%0,%1,%2,%3}, [%4];"
        : "=r"(r[0]), "=r"(r[1]), "=r"(r[2]), "=r"(r[3]) : "r"(saddr));
}
__device__ __forceinline__ uint32_t h2u(__half2 h) { return *reinterpret_cast<uint32_t*>(&h); }
__device__ __forceinline__ float sigm(float x)  { return 1.f / (1.f + __expf(-x)); }
__device__ __forceinline__ float tanhq(float x) { return 1.f - 2.f / (1.f + __expf(2.f * x)); }

// ---------------- conversions ----------------
__global__ void round_f16(const float* __restrict__ in, __half* __restrict__ out, int n4) {
    int i = blockIdx.x * blockDim.x + threadIdx.x;
    if (i < n4) {
        float4 v = ((const float4*)in)[i];
        *(__half2*)(out + (size_t)i * 4)     = __floats2half2_rn(v.x, v.y);
        *(__half2*)(out + (size_t)i * 4 + 2) = __floats2half2_rn(v.z, v.w);
    }
}
__global__ void cvt_x(const float* __restrict__ in, __half* __restrict__ out, int n8) {
    const int stride = gridDim.x * blockDim.x;
    for (int i = blockIdx.x * blockDim.x + threadIdx.x; i < n8; i += stride) {
        float4 a = ((const float4*)in)[(size_t)2 * i];
        float4 b = ((const float4*)in)[(size_t)2 * i + 1];
        uint4 o;
        o.x = h2u(__floats2half2_rn(a.x, a.y));
        o.y = h2u(__floats2half2_rn(a.z, a.w));
        o.z = h2u(__floats2half2_rn(b.x, b.y));
        o.w = h2u(__floats2half2_rn(b.z, b.w));
        ((uint4*)out)[i] = o;
    }
}

// ---------------- GEMM fp16 (all 4 feed-forward GEMMs) — R10-proven ----------
template<bool THRESH, bool OUT16>
__global__ void __launch_bounds__(256, 2)
gemm_h(const __half* __restrict__ Ag, const __half* __restrict__ Bg,
       const float* __restrict__ bias, void* __restrict__ Cgv,
       int M, int N, int K, int ntiles, int tn)
{
    extern __shared__ __half smh[];
    constexpr int AS = 128 * LDH;
    constexpr int SS = 2 * AS;
    const int tid  = threadIdx.x;
    const int lane = tid & 31, warp = tid >> 5;
    const int wr = warp >> 1, wc = warp & 1;
    const int grp = lane >> 2, tig = lane & 3;
    const int sel = lane >> 3, rw = lane & 7;
    const int NT = K >> 5;
    const uint32_t smb = smem_u32(smh);

    int lr[2], lk[2];
#pragma unroll
    for (int i = 0; i < 2; i++) { int l = tid + i * 256; lr[i] = l >> 2; lk[i] = (l & 3) << 3; }

    uint32_t adA[2], adB[4];
#pragma unroll
    for (int mi = 0; mi < 2; mi++) {
        const int row = wr * 32 + mi * 16 + ((sel & 1) << 3) + rw;
        adA[mi] = smb + (uint32_t)(row * LDH + ((sel >> 1) << 3)) * 2u;
    }
#pragma unroll
    for (int p = 0; p < 4; p++) {
        const int row = wc * 64 + p * 16 + ((sel & 1) << 3) + rw;
        adB[p] = smb + (uint32_t)(AS + row * LDH + ((sel >> 1) << 3)) * 2u;
    }

    for (int tile = blockIdx.x; tile < ntiles; tile += gridDim.x) {
        const int bm = (tile / tn) << 7;
        const int bn = (tile % tn) << 7;
        const __half* Ab = Ag + (size_t)bm * K;
        const __half* Bb = Bg + (size_t)bn * K;

        auto issue = [&](int kt) {
            const int st = kt & 3;
            const int go = kt << 5;
#pragma unroll
            for (int i = 0; i < 2; i++) {
                uint32_t sa = smb + (uint32_t)(st * SS + lr[i] * LDH + lk[i]) * 2u;
                cp16(sa,           Ab + (size_t)lr[i] * K + go + lk[i]);
                cp16(sa + AS * 2u, Bb + (size_t)lr[i] * K + go + lk[i]);
            }
            asm volatile("cp.async.commit_group;\n");
        };

        float acc[2][8][4];
#pragma unroll
        for (int a = 0; a < 2; a++)
#pragma unroll
            for (int b = 0; b < 8; b++)
#pragma unroll
                for (int c = 0; c < 4; c++) acc[a][b][c] = 0.f;

        issue(0); issue(1); issue(2);

        for (int kt = 0; kt < NT; kt++) {
            const int rem = NT - 1 - kt;
            if (rem >= 2)      asm volatile("cp.async.wait_group 2;\n");
            else if (rem == 1) asm volatile("cp.async.wait_group 1;\n");
            else               asm volatile("cp.async.wait_group 0;\n");
            __syncthreads();
            if (kt + 3 < NT) issue(kt + 3);

            const uint32_t stoff = (uint32_t)((kt & 3) * SS) * 2u;
#pragma unroll
            for (int ks = 0; ks < 2; ks++) {
                const uint32_t koff = stoff + (uint32_t)(ks * 16) * 2u;
                uint32_t af[2][4], bq[4][4];
#pragma unroll
                for (int mi = 0; mi < 2; mi++) ldsm4(af[mi], adA[mi] + koff);
#pragma unroll
                for (int p = 0; p < 4; p++) ldsm4(bq[p], adB[p] + koff);
#pragma unroll
                for (int mi = 0; mi < 2; mi++)
#pragma unroll
                    for (int p = 0; p < 4; p++) {
                        mma_f16(acc[mi][2 * p],     af[mi], bq[p][0], bq[p][2]);
                        mma_f16(acc[mi][2 * p + 1], af[mi], bq[p][1], bq[p][3]);
                    }
            }
        }
        __syncthreads();

#pragma unroll
        for (int mi = 0; mi < 2; mi++) {
            const int r0 = bm + wr * 32 + mi * 16 + grp;
#pragma unroll
            for (int ni = 0; ni < 8; ni++) {
                const int c0 = bn + wc * 64 + ni * 8 + tig * 2;
                const float b0 = bias[c0], b1 = bias[c0 + 1];
                float v00 = acc[mi][ni][0] + b0, v01 = acc[mi][ni][1] + b1;
                float v10 = acc[mi][ni][2] + b0, v11 = acc[mi][ni][3] + b1;
                if (THRESH) {
                    v00 = (v00 > kThr) ? v00 : 0.f;  v01 = (v01 > kThr) ? v01 : 0.f;
                    v10 = (v10 > kThr) ? v10 : 0.f;  v11 = (v11 > kThr) ? v11 : 0.f;
                }
                if (OUT16) {
                    __half* Cg = (__half*)Cgv;
                    *(__half2*)&Cg[(size_t)r0 * N + c0]       = __floats2half2_rn(v00, v01);
                    *(__half2*)&Cg[(size_t)(r0 + 8) * N + c0] = __floats2half2_rn(v10, v11);
                } else {
                    float* Cg = (float*)Cgv;
                    *(float2*)&Cg[(size_t)r0 * N + c0]       = make_float2(v00, v01);
                    *(float2*)&Cg[(size_t)(r0 + 8) * N + c0] = make_float2(v10, v11);
                }
            }
        }
    }
}

// ---------------- grid barrier (grid=128 <= 148 SMs, 1 CTA/SM) ----------------
__device__ __forceinline__ void grid_barrier() {
    __syncthreads();
    if (threadIdx.x == 0) {
        unsigned gen = *((volatile unsigned*)&g_bar_gen);
        __threadfence();
        if (atomicAdd(&g_bar_count, 1u) == gridDim.x - 1) {
            atomicExch(&g_bar_count, 0u);
            __threadfence();
            atomicAdd(&g_bar_gen, 1u);
        } else {
            while (*((volatile unsigned*)&g_bar_gen) == gen) { __nanosleep(32); }
            __threadfence();
        }
    }
    __syncthreads();
}

// ---------------- persistent fused GRU (fp16 operands + fp16 gi) --------------
__global__ void __launch_bounds__(256, 1)
gru_persistent(const __half* __restrict__ gi, const float* __restrict__ w_hh,
               const float* __restrict__ b_hh,
               __half* __restrict__ hA, __half* __restrict__ hB)
{
    extern __shared__ __half smg[];
    __half* ws = smg;                          // [96][WS_LDH]
    __half* ht = smg + 96 * WS_LDH;            // 3 stages x [128][HT_LDH]
    constexpr int HTS = 128 * HT_LDH;

    const int tid  = threadIdx.x;
    const int lane = tid & 31, warp = tid >> 5;
    const int grp = lane >> 2, tig = lane & 3;
    const int sel = lane >> 3, rw = lane & 7;
    const int mt = blockIdx.x >> 4;
    const int jc = blockIdx.x & 15;
    const int m0 = mt * 128, j0 = jc * 32;

    for (int i4 = tid; i4 < 96 * 128; i4 += 256) {
        const int row = i4 >> 7, k4 = (i4 & 127) << 2;
        const int g = row >> 5, c = row & 31;
        float4 v = *(const float4*)(w_hh + (size_t)(g * kD + j0 + c) * kD + k4);
        *(__half2*)(ws + row * WS_LDH + k4)     = __floats2half2_rn(v.x, v.y);
        *(__half2*)(ws + row * WS_LDH + k4 + 2) = __floats2half2_rn(v.z, v.w);
    }

    float bhh0[12], bhh1[12];
#pragma unroll
    for (int ni = 0; ni < 12; ni++) {
        const int g = ni >> 2, j = j0 + (ni & 3) * 8 + tig * 2;
        bhh0[ni] = b_hh[g * kD + j];
        bhh1[ni] = b_hh[g * kD + j + 1];
    }
    __syncthreads();

    int lr[2], lk[2];
#pragma unroll
    for (int i = 0; i < 2; i++) { int l = tid + i * 256; lr[i] = l >> 2; lk[i] = (l & 3) << 3; }
    const uint32_t smb_ht = smem_u32(ht);
    const uint32_t smb_ws = smem_u32(ws);

    uint32_t adA, adB[6];
    {
        const int row = warp * 16 + ((sel & 1) << 3) + rw;
        adA = smb_ht + (uint32_t)(row * HT_LDH + ((sel >> 1) << 3)) * 2u;
    }
#pragma unroll
    for (int p = 0; p < 6; p++) {
        const int row = p * 16 + ((sel & 1) << 3) + rw;
        adB[p] = smb_ws + (uint32_t)(row * WS_LDH + ((sel >> 1) << 3)) * 2u;
    }

    for (int t = 0; t < kL; t++) {
        __half* src = (t & 1) ? hA : hB;
        __half* dst = (t & 1) ? hB : hA;

        float acc[12][4];
#pragma unroll
        for (int a = 0; a < 12; a++)
#pragma unroll
            for (int c = 0; c < 4; c++) acc[a][c] = 0.f;

        if (t > 0) {
            const __half* Ab = src + (size_t)m0 * kD;
            auto issue = [&](int kt) {
                const int st = kt % 3;
                const int go = kt << 5;
#pragma unroll
                for (int i = 0; i < 2; i++) {
                    uint32_t sa = smb_ht + (uint32_t)(st * HTS + lr[i] * HT_LDH + lk[i]) * 2u;
                    cp16(sa, Ab + (size_t)lr[i] * kD + go + lk[i]);
                }
                asm volatile("cp.async.commit_group;\n");
            };
            issue(0); issue(1);

            for (int kt = 0; kt < 16; kt++) {
                if (kt + 1 < 16) asm volatile("cp.async.wait_group 1;\n");
                else             asm volatile("cp.async.wait_group 0;\n");
                __syncthreads();
                if (kt + 2 < 16) issue(kt + 2);

                const uint32_t stoff = (uint32_t)((kt % 3) * HTS) * 2u;
                const uint32_t kbyte = (uint32_t)(kt << 5) * 2u;
#pragma unroll
                for (int ks = 0; ks < 2; ks++) {
                    const uint32_t ko = (uint32_t)(ks * 16) * 2u;
                    uint32_t af[4], bq[6][4];
                    ldsm4(af, adA + stoff + ko);
#pragma unroll
                    for (int p = 0; p < 6; p++) ldsm4(bq[p], adB[p] + kbyte + ko);
#pragma unroll
                    for (int p = 0; p < 6; p++) {
                        mma_f16(acc[2 * p],     af, bq[p][0], bq[p][2]);
                        mma_f16(acc[2 * p + 1], af, bq[p][1], bq[p][3]);
                    }
                }
            }
            __syncthreads();
        }

#pragma unroll
        for (int q = 0; q < 4; q++) {
#pragma unroll
            for (int s = 0; s < 2; s++) {
                const int b  = m0 + warp * 16 + grp + s * 8;
                const int jj = j0 + q * 8 + tig * 2;
                const __half* gib = gi + ((size_t)b * kL + t) * (3 * kD);
                const float2 gr = __half22float2(*(const __half2*)(gib + jj));
                const float2 gz = __half22float2(*(const __half2*)(gib + kD + jj));
                const float2 gn = __half22float2(*(const __half2*)(gib + 2 * kD + jj));
                float2 hp = make_float2(0.f, 0.f);
                if (t > 0) hp = __half22float2(*(const __half2*)(src + (size_t)b * kD + jj));
                const float r0 = sigm(gr.x + acc[q][2 * s]     + bhh0[q]);
                const float r1 = sigm(gr.y + acc[q][2 * s + 1] + bhh1[q]);
                const float z0 = sigm(gz.x + acc[q + 4][2 * s]     + bhh0[q + 4]);
                const float z1 = sigm(gz.y + acc[q + 4][2 * s + 1] + bhh1[q + 4]);
                const float n0 = tanhq(gn.x + r0 * (acc[q + 8][2 * s]     + bhh0[q + 8]));
                const float n1 = tanhq(gn.y + r1 * (acc[q + 8][2 * s + 1] + bhh1[q + 8]));
                const float h0 = (1.f - z0) * n0 + z0 * hp.x;
                const float h1 = (1.f - z1) * n1 + z1 * hp.y;
                *(__half2*)(dst + (size_t)b * kD + jj) = __floats2half2_rn(h0, h1);
            }
        }
        if (t < kL - 1) grid_barrier();
    }
}

// ---------------- host ----------------
extern "C" void kernel_launch(void* const* d_in, const int* in_sizes, int n_in,
                              void* d_out, int out_size)
{
    (void)in_sizes; (void)n_in; (void)out_size;
    const float* x     = (const float*)d_in[0];
    const float* w1    = (const float*)d_in[1];
    const float* b1    = (const float*)d_in[2];
    const float* w2    = (const float*)d_in[3];
    const float* b2    = (const float*)d_in[4];
    const float* w_ih  = (const float*)d_in[5];
    const float* w_hh  = (const float*)d_in[6];
    const float* b_ih  = (const float*)d_in[7];
    const float* b_hh  = (const float*)d_in[8];
    const float* lin_w = (const float*)d_in[9];
    const float* lin_b = (const float*)d_in[10];
    float* out = (float*)d_out;

    __half *xh, *h1, *h2, *gi, *hA, *hB, *rw1h, *rw2h, *rwihh, *rlinh;
    cudaGetSymbolAddress((void**)&xh,    g_xh);
    cudaGetSymbolAddress((void**)&h1,    g_h1);
    cudaGetSymbolAddress((void**)&h2,    g_h2);
    cudaGetSymbolAddress((void**)&gi,    g_gi);
    cudaGetSymbolAddress((void**)&hA,    g_hA);
    cudaGetSymbolAddress((void**)&hB,    g_hB);
    cudaGetSymbolAddress((void**)&rw1h,  g_rw1h);
    cudaGetSymbolAddress((void**)&rw2h,  g_rw2h);
    cudaGetSymbolAddress((void**)&rwihh, g_rwihh);
    cudaGetSymbolAddress((void**)&rlinh, g_rlinh);

    constexpr int H16_SMEM  = 4 * 2 * 128 * LDH * 2;                    // 81920
    constexpr int GRU_SMEM  = (96 * WS_LDH + 3 * 128 * HT_LDH) * 2;     // 130560
    cudaFuncSetAttribute(gemm_h<true,  true >, cudaFuncAttributeMaxDynamicSharedMemorySize, H16_SMEM);
    cudaFuncSetAttribute(gemm_h<false, true >, cudaFuncAttributeMaxDynamicSharedMemorySize, H16_SMEM);
    cudaFuncSetAttribute(gemm_h<false, false>, cudaFuncAttributeMaxDynamicSharedMemorySize, H16_SMEM);
    cudaFuncSetAttribute(gru_persistent,       cudaFuncAttributeMaxDynamicSharedMemorySize, GRU_SMEM);

    // One worker stream + events, created once (host-side objects, not device mem)
    static cudaStream_t s2 = nullptr;
    static cudaEvent_t evF = nullptr, evJ = nullptr, evC[kChunks] = {};
    if (!s2) {
        cudaStreamCreateWithFlags(&s2, cudaStreamNonBlocking);
        cudaEventCreateWithFlags(&evF, cudaEventDisableTiming);
        cudaEventCreateWithFlags(&evJ, cudaEventDisableTiming);
        for (int c = 0; c < kChunks; c++)
            cudaEventCreateWithFlags(&evC[c], cudaEventDisableTiming);
    }

    const int tm = kM / 128;   // 208
    constexpr int n8chunk = kRowsPerChunk * kA / 8;

    // fork worker stream off the (captured) origin stream
    cudaEventRecord(evF, 0);
    cudaStreamWaitEvent(s2, evF, 0);

    // #1: w1 -> fp16 on s2 (must precede conv1 chunks, same stream => ordered)
    round_f16<<<(kC1 * kA / 4 + 255) / 256, 256, 0, s2>>>(w1, rw1h, kC1 * kA / 4);

    // #2, #3: first two x-chunks on origin stream
    cvt_x<<<2048, 256>>>(x, xh, n8chunk);
    cudaEventRecord(evC[0], 0);
    cvt_x<<<2048, 256>>>(x + (size_t)1 * kRowsPerChunk * kA,
                         xh + (size_t)1 * kRowsPerChunk * kA, n8chunk);
    cudaEventRecord(evC[1], 0);

    // #4: conv1 chunk 0 on s2 (ncu-captured slot)
    cudaStreamWaitEvent(s2, evC[0], 0);
    gemm_h<true, true><<<kTilesPerChunk * 2, 256, H16_SMEM, s2>>>(
        xh, rw1h, b1, h1, kRowsPerChunk, kC1, kA, kTilesPerChunk * 2, 2);

    // #5: x-chunk 2 ; #6: conv1 chunk 1 ; #7: x-chunk 3 ; then remaining conv1
    cvt_x<<<2048, 256>>>(x + (size_t)2 * kRowsPerChunk * kA,
                         xh + (size_t)2 * kRowsPerChunk * kA, n8chunk);
    cudaEventRecord(evC[2], 0);
    cudaStreamWaitEvent(s2, evC[1], 0);
    gemm_h<true, true><<<kTilesPerChunk * 2, 256, H16_SMEM, s2>>>(
        xh + (size_t)1 * kRowsPerChunk * kA, rw1h, b1,
        h1 + (size_t)1 * kRowsPerChunk * kC1, kRowsPerChunk, kC1, kA, kTilesPerChunk * 2, 2);
    cvt_x<<<2048, 256>>>(x + (size_t)3 * kRowsPerChunk * kA,
                         xh + (size_t)3 * kRowsPerChunk * kA, n8chunk);
    cudaEventRecord(evC[3], 0);
    cudaStreamWaitEvent(s2, evC[2], 0);
    gemm_h<true, true><<<kTilesPerChunk * 2, 256, H16_SMEM, s2>>>(
        xh + (size_t)2 * kRowsPerChunk * kA, rw1h, b1,
        h1 + (size_t)2 * kRowsPerChunk * kC1, kRowsPerChunk, kC1, kA, kTilesPerChunk * 2, 2);
    cudaStreamWaitEvent(s2, evC[3], 0);
    gemm_h<true, true><<<kTilesPerChunk * 2, 256, H16_SMEM, s2>>>(
        xh + (size_t)3 * kRowsPerChunk * kA, rw1h, b1,
        h1 + (size_t)3 * kRowsPerChunk * kC1, kRowsPerChunk, kC1, kA, kTilesPerChunk * 2, 2);

    // remaining weight converts on origin stream (overlap conv1 tail)
    round_f16<<<(kD * kC1 / 4 + 255) / 256, 256>>>(w2, rw2h, kD * kC1 / 4);
    round_f16<<<(3 * kD * kD / 4 + 255) / 256, 256>>>(w_ih, rwihh, 3 * kD * kD / 4);
    round_f16<<<(kE * kD / 4 + 255) / 256, 256>>>(lin_w, rlinh, kE * kD / 4);

    // join worker stream back into origin
    cudaEventRecord(evJ, s2);
    cudaStreamWaitEvent(0, evJ, 0);

    // conv2 [26624,256] x [512,256]^T (fp16, thresh, fp16 out)
    gemm_h<true, true ><<<tm * 4, 256, H16_SMEM>>>(h1, rw2h, b2, h2, kM, kD, kC1, tm * 4, 4);
    // gi [26624,512] x [1536,512]^T (fp16 in/out)
    gemm_h<false, true ><<<tm * 12, 256, H16_SMEM>>>(h2, rwihh, b_ih, gi, kM, 3 * kD, kD, tm * 12, 12);
    // fused persistent GRU (26 steps; kL even -> final h lands in hB)
    gru_persistent<<<128, 256, GRU_SMEM>>>(gi, w_hh, b_hh, hA, hB);
    // out = h_last @ lin_w^T + lin_b (fp16 in, f32 out)
    gemm_h<false, false><<<8 * 8, 256, H16_SMEM>>>(hB, rlinh, lin_b, out, kB, kE, kD, 8 * 8, 8);
}

// round 16
// speedup vs baseline: 1.2111x; 1.2111x over previous
#include <cuda_runtime.h>
#include <cuda_fp16.h>
#include <cstdint>

namespace {
constexpr int kB  = 1024;
constexpr int kL  = 26;
constexpr int kA  = 8192;
constexpr int kC1 = 256;
constexpr int kD  = 512;
constexpr int kE  = 1024;
constexpr int kM  = kB * kL;      // 26624
constexpr float kThr = 1e-6f;
constexpr int LDH   = 40;         // fp16 gemm smem row stride (halves): BK=32 + 8
constexpr int WS_LDH = 520;       // GRU resident w_hh stride (halves)
constexpr int HT_LDH = 72;        // GRU h-tile stride (halves): BK=64 + 8 (144B rows: conflict-free)
}

// ---------------- scratch (allocation-free) ----------------
__device__ __half g_xh[(size_t)kM * kA];        // x in fp16
__device__ __half g_h1[(size_t)kM * kC1];
__device__ __half g_h2[(size_t)kM * kD];
__device__ __half g_gi[(size_t)kM * 3 * kD];
__device__ __half g_hA[(size_t)kB * kD];
__device__ __half g_hB[(size_t)kB * kD];
__device__ __half g_rw1h[(size_t)kC1 * kA];
__device__ __half g_rw2h[(size_t)kD * kC1];
__device__ __half g_rwihh[(size_t)3 * kD * kD];
__device__ __half g_rlinh[(size_t)kE * kD];
__device__ unsigned g_cnt[8][32];               // per-mt barrier counters (padded lines)
__device__ unsigned g_gen[8][32];

// ---------------- helpers ----------------
__device__ __forceinline__ void mma_f16(float d[4], const uint32_t a[4], uint32_t b0, uint32_t b1) {
    asm volatile(
        "mma.sync.aligned.m16n8k16.row.col.f32.f16.f16.f32 "
        "{%0,%1,%2,%3}, {%4,%5,%6,%7}, {%8,%9}, {%0,%1,%2,%3};"
        : "+f"(d[0]), "+f"(d[1]), "+f"(d[2]), "+f"(d[3])
        : "r"(a[0]), "r"(a[1]), "r"(a[2]), "r"(a[3]), "r"(b0), "r"(b1));
}
__device__ __forceinline__ void cp16(uint32_t saddr, const void* g) {
    asm volatile("cp.async.cg.shared.global [%0], [%1], 16;\n" :: "r"(saddr), "l"(g));
}
__device__ __forceinline__ uint32_t smem_u32(const void* p) {
    uint32_t a;
    asm("{ .reg .u64 t; cvta.to.shared.u64 t, %1; cvt.u32.u64 %0, t; }" : "=r"(a) : "l"(p));
    return a;
}
__device__ __forceinline__ void ldsm4(uint32_t r[4], uint32_t saddr) {
    asm volatile("ldmatrix.sync.aligned.m8n8.x4.shared.b16 {%0,%1,%2,%3}, [%4];"
        : "=r"(r[0]), "=r"(r[1]), "=r"(r[2]), "=r"(r[3]) : "r"(saddr));
}
__device__ __forceinline__ uint32_t h2u(__half2 h) { return *reinterpret_cast<uint32_t*>(&h); }
__device__ __forceinline__ float sigm(float x)  { return 1.f / (1.f + __expf(-x)); }
__device__ __forceinline__ float tanhq(float x) { return 1.f - 2.f / (1.f + __expf(2.f * x)); }

// ---------------- conversions ----------------
__global__ void round_f16(const float* __restrict__ in, __half* __restrict__ out, int n4) {
    int i = blockIdx.x * blockDim.x + threadIdx.x;
    if (i < n4) {
        float4 v = ((const float4*)in)[i];
        *(__half2*)(out + (size_t)i * 4)     = __floats2half2_rn(v.x, v.y);
        *(__half2*)(out + (size_t)i * 4 + 2) = __floats2half2_rn(v.z, v.w);
    }
}
__global__ void cvt_x(const float* __restrict__ in, __half* __restrict__ out, int n8) {
    const int stride = gridDim.x * blockDim.x;
    for (int i = blockIdx.x * blockDim.x + threadIdx.x; i < n8; i += stride) {
        float4 a = ((const float4*)in)[(size_t)2 * i];
        float4 b = ((const float4*)in)[(size_t)2 * i + 1];
        uint4 o;
        o.x = h2u(__floats2half2_rn(a.x, a.y));
        o.y = h2u(__floats2half2_rn(a.z, a.w));
        o.z = h2u(__floats2half2_rn(b.x, b.y));
        o.w = h2u(__floats2half2_rn(b.z, b.w));
        ((uint4*)out)[i] = o;
    }
}

// ---------------- GEMM fp16 (all 4 feed-forward GEMMs) — R10-proven ----------
template<bool THRESH, bool OUT16>
__global__ void __launch_bounds__(256, 2)
gemm_h(const __half* __restrict__ Ag, const __half* __restrict__ Bg,
       const float* __restrict__ bias, void* __restrict__ Cgv,
       int M, int N, int K, int ntiles, int tn)
{
    extern __shared__ __half smh[];
    constexpr int AS = 128 * LDH;
    constexpr int SS = 2 * AS;
    const int tid  = threadIdx.x;
    const int lane = tid & 31, warp = tid >> 5;
    const int wr = warp >> 1, wc = warp & 1;
    const int grp = lane >> 2, tig = lane & 3;
    const int sel = lane >> 3, rw = lane & 7;
    const int NT = K >> 5;
    const uint32_t smb = smem_u32(smh);

    int lr[2], lk[2];
#pragma unroll
    for (int i = 0; i < 2; i++) { int l = tid + i * 256; lr[i] = l >> 2; lk[i] = (l & 3) << 3; }

    uint32_t adA[2], adB[4];
#pragma unroll
    for (int mi = 0; mi < 2; mi++) {
        const int row = wr * 32 + mi * 16 + ((sel & 1) << 3) + rw;
        adA[mi] = smb + (uint32_t)(row * LDH + ((sel >> 1) << 3)) * 2u;
    }
#pragma unroll
    for (int p = 0; p < 4; p++) {
        const int row = wc * 64 + p * 16 + ((sel & 1) << 3) + rw;
        adB[p] = smb + (uint32_t)(AS + row * LDH + ((sel >> 1) << 3)) * 2u;
    }

    for (int tile = blockIdx.x; tile < ntiles; tile += gridDim.x) {
        const int bm = (tile / tn) << 7;
        const int bn = (tile % tn) << 7;
        const __half* Ab = Ag + (size_t)bm * K;
        const __half* Bb = Bg + (size_t)bn * K;

        auto issue = [&](int kt) {
            const int st = kt & 3;
            const int go = kt << 5;
#pragma unroll
            for (int i = 0; i < 2; i++) {
                uint32_t sa = smb + (uint32_t)(st * SS + lr[i] * LDH + lk[i]) * 2u;
                cp16(sa,           Ab + (size_t)lr[i] * K + go + lk[i]);
                cp16(sa + AS * 2u, Bb + (size_t)lr[i] * K + go + lk[i]);
            }
            asm volatile("cp.async.commit_group;\n");
        };

        float acc[2][8][4];
#pragma unroll
        for (int a = 0; a < 2; a++)
#pragma unroll
            for (int b = 0; b < 8; b++)
#pragma unroll
                for (int c = 0; c < 4; c++) acc[a][b][c] = 0.f;

        issue(0); issue(1); issue(2);

        for (int kt = 0; kt < NT; kt++) {
            const int rem = NT - 1 - kt;
            if (rem >= 2)      asm volatile("cp.async.wait_group 2;\n");
            else if (rem == 1) asm volatile("cp.async.wait_group 1;\n");
            else               asm volatile("cp.async.wait_group 0;\n");
            __syncthreads();
            if (kt + 3 < NT) issue(kt + 3);

            const uint32_t stoff = (uint32_t)((kt & 3) * SS) * 2u;
#pragma unroll
            for (int ks = 0; ks < 2; ks++) {
                const uint32_t koff = stoff + (uint32_t)(ks * 16) * 2u;
                uint32_t af[2][4], bq[4][4];
#pragma unroll
                for (int mi = 0; mi < 2; mi++) ldsm4(af[mi], adA[mi] + koff);
#pragma unroll
                for (int p = 0; p < 4; p++) ldsm4(bq[p], adB[p] + koff);
#pragma unroll
                for (int mi = 0; mi < 2; mi++)
#pragma unroll
                    for (int p = 0; p < 4; p++) {
                        mma_f16(acc[mi][2 * p],     af[mi], bq[p][0], bq[p][2]);
                        mma_f16(acc[mi][2 * p + 1], af[mi], bq[p][1], bq[p][3]);
                    }
            }
        }
        __syncthreads();

#pragma unroll
        for (int mi = 0; mi < 2; mi++) {
            const int r0 = bm + wr * 32 + mi * 16 + grp;
#pragma unroll
            for (int ni = 0; ni < 8; ni++) {
                const int c0 = bn + wc * 64 + ni * 8 + tig * 2;
                const float b0 = bias[c0], b1 = bias[c0 + 1];
                float v00 = acc[mi][ni][0] + b0, v01 = acc[mi][ni][1] + b1;
                float v10 = acc[mi][ni][2] + b0, v11 = acc[mi][ni][3] + b1;
                if (THRESH) {
                    v00 = (v00 > kThr) ? v00 : 0.f;  v01 = (v01 > kThr) ? v01 : 0.f;
                    v10 = (v10 > kThr) ? v10 : 0.f;  v11 = (v11 > kThr) ? v11 : 0.f;
                }
                if (OUT16) {
                    __half* Cg = (__half*)Cgv;
                    *(__half2*)&Cg[(size_t)r0 * N + c0]       = __floats2half2_rn(v00, v01);
                    *(__half2*)&Cg[(size_t)(r0 + 8) * N + c0] = __floats2half2_rn(v10, v11);
                } else {
                    float* Cg = (float*)Cgv;
                    *(float2*)&Cg[(size_t)r0 * N + c0]       = make_float2(v00, v01);
                    *(float2*)&Cg[(size_t)(r0 + 8) * N + c0] = make_float2(v10, v11);
                }
            }
        }
    }
}

// ---------------- per-mt group barrier (16 CTAs per group, 8 groups) ----------
__device__ __forceinline__ void group_barrier(int mt) {
    __syncthreads();
    if (threadIdx.x == 0) {
        unsigned gen = *((volatile unsigned*)&g_gen[mt][0]);
        __threadfence();
        if (atomicAdd(&g_cnt[mt][0], 1u) == 15u) {
            atomicExch(&g_cnt[mt][0], 0u);
            __threadfence();
            atomicAdd(&g_gen[mt][0], 1u);
        } else {
            while (*((volatile unsigned*)&g_gen[mt][0]) == gen) { __nanosleep(32); }
            __threadfence();
        }
    }
    __syncthreads();
}

// ---------------- persistent fused GRU (fp16, BK=64, per-mt barrier) ----------
// grid=128: CTA owns batch rows [mt*128,+128) x gate cols [jc*32,+32).  Only the
// 16 CTAs sharing mt exchange data across steps -> group barrier, not global.
__global__ void __launch_bounds__(256, 1)
gru_persistent(const __half* __restrict__ gi, const float* __restrict__ w_hh,
               const float* __restrict__ b_hh,
               __half* __restrict__ hA, __half* __restrict__ hB)
{
    extern __shared__ __half smg[];
    __half* ws = smg;                          // [96][WS_LDH]
    __half* ht = smg + 96 * WS_LDH;            // 3 stages x [128][HT_LDH]
    constexpr int HTS = 128 * HT_LDH;

    const int tid  = threadIdx.x;
    const int lane = tid & 31, warp = tid >> 5;
    const int grp = lane >> 2, tig = lane & 3;
    const int sel = lane >> 3, rw = lane & 7;
    const int mt = blockIdx.x >> 4;
    const int jc = blockIdx.x & 15;
    const int m0 = mt * 128, j0 = jc * 32;

    for (int i4 = tid; i4 < 96 * 128; i4 += 256) {
        const int row = i4 >> 7, k4 = (i4 & 127) << 2;
        const int g = row >> 5, c = row & 31;
        float4 v = *(const float4*)(w_hh + (size_t)(g * kD + j0 + c) * kD + k4);
        *(__half2*)(ws + row * WS_LDH + k4)     = __floats2half2_rn(v.x, v.y);
        *(__half2*)(ws + row * WS_LDH + k4 + 2) = __floats2half2_rn(v.z, v.w);
    }

    float bhh0[12], bhh1[12];
#pragma unroll
    for (int ni = 0; ni < 12; ni++) {
        const int g = ni >> 2, j = j0 + (ni & 3) * 8 + tig * 2;
        bhh0[ni] = b_hh[g * kD + j];
        bhh1[ni] = b_hh[g * kD + j + 1];
    }
    __syncthreads();

    // h-tile cp.async mapping: 128 rows x 8 chunks of 16B (BK=64 halves)
    int lr[4], lk[4];
#pragma unroll
    for (int i = 0; i < 4; i++) { int l = tid + i * 256; lr[i] = l >> 3; lk[i] = (l & 7) << 3; }
    const uint32_t smb_ht = smem_u32(ht);
    const uint32_t smb_ws = smem_u32(ws);

    uint32_t adA, adB[6];
    {
        const int row = warp * 16 + ((sel & 1) << 3) + rw;
        adA = smb_ht + (uint32_t)(row * HT_LDH + ((sel >> 1) << 3)) * 2u;
    }
#pragma unroll
    for (int p = 0; p < 6; p++) {
        const int row = p * 16 + ((sel & 1) << 3) + rw;
        adB[p] = smb_ws + (uint32_t)(row * WS_LDH + ((sel >> 1) << 3)) * 2u;
    }

    for (int t = 0; t < kL; t++) {
        __half* src = (t & 1) ? hA : hB;
        __half* dst = (t & 1) ? hB : hA;

        float acc[12][4];
#pragma unroll
        for (int a = 0; a < 12; a++)
#pragma unroll
            for (int c = 0; c < 4; c++) acc[a][c] = 0.f;

        if (t > 0) {
            const __half* Ab = src + (size_t)m0 * kD;
            auto issue = [&](int kt) {        // kt in 0..7, BK=64 halves
                const int st = kt % 3;
                const int go = kt << 6;
#pragma unroll
                for (int i = 0; i < 4; i++) {
                    uint32_t sa = smb_ht + (uint32_t)(st * HTS + lr[i] * HT_LDH + lk[i]) * 2u;
                    cp16(sa, Ab + (size_t)lr[i] * kD + go + lk[i]);
                }
                asm volatile("cp.async.commit_group;\n");
            };
            issue(0); issue(1);

            for (int kt = 0; kt < 8; kt++) {
                if (kt + 1 < 8) asm volatile("cp.async.wait_group 1;\n");
                else            asm volatile("cp.async.wait_group 0;\n");
                __syncthreads();
                if (kt + 2 < 8) issue(kt + 2);

                const uint32_t stoff = (uint32_t)((kt % 3) * HTS) * 2u;
                const uint32_t kbyte = (uint32_t)(kt << 6) * 2u;
#pragma unroll
                for (int ks = 0; ks < 4; ks++) {   // four k16 steps
                    const uint32_t ko = (uint32_t)(ks * 16) * 2u;
                    uint32_t af[4], bq[6][4];
                    ldsm4(af, adA + stoff + ko);
#pragma unroll
                    for (int p = 0; p < 6; p++) ldsm4(bq[p], adB[p] + kbyte + ko);
#pragma unroll
                    for (int p = 0; p < 6; p++) {
                        mma_f16(acc[2 * p],     af, bq[p][0], bq[p][2]);
                        mma_f16(acc[2 * p + 1], af, bq[p][1], bq[p][3]);
                    }
                }
            }
            __syncthreads();
        }

        // fused gate update: acc[q]=gh_r, acc[q+4]=gh_z, acc[q+8]=gh_n
#pragma unroll
        for (int q = 0; q < 4; q++) {
#pragma unroll
            for (int s = 0; s < 2; s++) {
                const int b  = m0 + warp * 16 + grp + s * 8;
                const int jj = j0 + q * 8 + tig * 2;
                const __half* gib = gi + ((size_t)b * kL + t) * (3 * kD);
                const float2 gr = __half22float2(*(const __half2*)(gib + jj));
                const float2 gz = __half22float2(*(const __half2*)(gib + kD + jj));
                const float2 gn = __half22float2(*(const __half2*)(gib + 2 * kD + jj));
                float2 hp = make_float2(0.f, 0.f);
                if (t > 0) hp = __half22float2(*(const __half2*)(src + (size_t)b * kD + jj));
                const float r0 = sigm(gr.x + acc[q][2 * s]     + bhh0[q]);
                const float r1 = sigm(gr.y + acc[q][2 * s + 1] + bhh1[q]);
                const float z0 = sigm(gz.x + acc[q + 4][2 * s]     + bhh0[q + 4]);
                const float z1 = sigm(gz.y + acc[q + 4][2 * s + 1] + bhh1[q + 4]);
                const float n0 = tanhq(gn.x + r0 * (acc[q + 8][2 * s]     + bhh0[q + 8]));
                const float n1 = tanhq(gn.y + r1 * (acc[q + 8][2 * s + 1] + bhh1[q + 8]));
                const float h0 = (1.f - z0) * n0 + z0 * hp.x;
                const float h1 = (1.f - z1) * n1 + z1 * hp.y;
                *(__half2*)(dst + (size_t)b * kD + jj) = __floats2half2_rn(h0, h1);
            }
        }
        if (t < kL - 1) group_barrier(mt);
    }
}

// ---------------- host ----------------
extern "C" void kernel_launch(void* const* d_in, const int* in_sizes, int n_in,
                              void* d_out, int out_size)
{
    (void)in_sizes; (void)n_in; (void)out_size;
    const float* x     = (const float*)d_in[0];
    const float* w1    = (const float*)d_in[1];
    const float* b1    = (const float*)d_in[2];
    const float* w2    = (const float*)d_in[3];
    const float* b2    = (const float*)d_in[4];
    const float* w_ih  = (const float*)d_in[5];
    const float* w_hh  = (const float*)d_in[6];
    const float* b_ih  = (const float*)d_in[7];
    const float* b_hh  = (const float*)d_in[8];
    const float* lin_w = (const float*)d_in[9];
    const float* lin_b = (const float*)d_in[10];
    float* out = (float*)d_out;

    __half *xh, *h1, *h2, *gi, *hA, *hB, *rw1h, *rw2h, *rwihh, *rlinh;
    cudaGetSymbolAddress((void**)&xh,    g_xh);
    cudaGetSymbolAddress((void**)&h1,    g_h1);
    cudaGetSymbolAddress((void**)&h2,    g_h2);
    cudaGetSymbolAddress((void**)&gi,    g_gi);
    cudaGetSymbolAddress((void**)&hA,    g_hA);
    cudaGetSymbolAddress((void**)&hB,    g_hB);
    cudaGetSymbolAddress((void**)&rw1h,  g_rw1h);
    cudaGetSymbolAddress((void**)&rw2h,  g_rw2h);
    cudaGetSymbolAddress((void**)&rwihh, g_rwihh);
    cudaGetSymbolAddress((void**)&rlinh, g_rlinh);

    constexpr int H16_SMEM  = 4 * 2 * 128 * LDH * 2;                    // 81920
    constexpr int GRU_SMEM  = (96 * WS_LDH + 3 * 128 * HT_LDH) * 2;     // 155136
    cudaFuncSetAttribute(gemm_h<true,  true >, cudaFuncAttributeMaxDynamicSharedMemorySize, H16_SMEM);
    cudaFuncSetAttribute(gemm_h<false, true >, cudaFuncAttributeMaxDynamicSharedMemorySize, H16_SMEM);
    cudaFuncSetAttribute(gemm_h<false, false>, cudaFuncAttributeMaxDynamicSharedMemorySize, H16_SMEM);
    cudaFuncSetAttribute(gru_persistent,       cudaFuncAttributeMaxDynamicSharedMemorySize, GRU_SMEM);

    const int tm = kM / 128;   // 208

    // 1: x -> fp16 (grid-stride streaming convert)
    cvt_x<<<4096, 256>>>(x, xh, kM * kA / 8);
    // 2-3: weight converts (keeps conv1 at ncu's captured slot #4)
    round_f16<<<(kC1 * kA / 4 + 255) / 256, 256>>>(w1, rw1h, kC1 * kA / 4);
    round_f16<<<(kD * kC1 / 4 + 255) / 256, 256>>>(w2, rw2h, kD * kC1 / 4);

    // 4: conv1 [26624,8192] x [256,8192]^T (fp16, thresh, fp16 out)
    gemm_h<true, true ><<<tm * 2, 256, H16_SMEM>>>(xh, rw1h, b1, h1, kM, kC1, kA, tm * 2, 2);

    // 5: w_ih convert
    round_f16<<<(3 * kD * kD / 4 + 255) / 256, 256>>>(w_ih, rwihh, 3 * kD * kD / 4);
    // 6: conv2 [26624,256] x [512,256]^T (fp16, thresh, fp16 out)
    gemm_h<true, true ><<<tm * 4, 256, H16_SMEM>>>(h1, rw2h, b2, h2, kM, kD, kC1, tm * 4, 4);
    // 7: gi [26624,512] x [1536,512]^T (fp16 in/out)
    gemm_h<false, true ><<<tm * 12, 256, H16_SMEM>>>(h2, rwihh, b_ih, gi, kM, 3 * kD, kD, tm * 12, 12);
    // 8: lin_w convert
    round_f16<<<(kE * kD / 4 + 255) / 256, 256>>>(lin_w, rlinh, kE * kD / 4);
    // 9: fused persistent GRU (26 steps; kL even -> final h lands in hB)
    gru_persistent<<<128, 256, GRU_SMEM>>>(gi, w_hh, b_hh, hA, hB);
    // 10: out = h_last @ lin_w^T + lin_b (fp16 in, f32 out)
    gemm_h<false, false><<<8 * 8, 256, H16_SMEM>>>(hB, rlinh, lin_b, out, kB, kE, kD, 8 * 8, 8);
}

// round 17
// speedup vs baseline: 1.2575x; 1.0384x over previous
#include <cuda_runtime.h>
#include <cuda_fp16.h>
#include <cstdint>

namespace {
constexpr int kB  = 1024;
constexpr int kL  = 26;
constexpr int kA  = 8192;
constexpr int kC1 = 256;
constexpr int kD  = 512;
constexpr int kE  = 1024;
constexpr int kM  = kB * kL;      // 26624
constexpr float kThr = 1e-6f;
constexpr int LDH   = 40;         // fp16 gemm smem row stride (halves): BK=32 + 8
constexpr int WS_LDH = 520;       // GRU resident w_hh stride (halves)
constexpr int HT_LDH = 72;        // GRU h-tile stride (halves): BK=64 + 8
}

// ---------------- scratch (allocation-free) ----------------
__device__ __half g_xh[(size_t)kM * kA];        // x in fp16
__device__ __half g_h1[(size_t)kM * kC1];
__device__ __half g_h2[(size_t)kM * kD];
__device__ __half g_gi[(size_t)kM * 3 * kD];
__device__ __half g_hA[(size_t)kB * kD];
__device__ __half g_hB[(size_t)kB * kD];
__device__ __half g_rw1h[(size_t)kC1 * kA];
__device__ __half g_rw2h[(size_t)kD * kC1];
__device__ __half g_rwihh[(size_t)3 * kD * kD];
__device__ __half g_rlinh[(size_t)kE * kD];
__device__ unsigned g_cnt[8][32];               // per-mt barrier counters (padded lines)
__device__ unsigned g_gen[8][32];

// ---------------- helpers ----------------
__device__ __forceinline__ void mma_f16(float d[4], const uint32_t a[4], uint32_t b0, uint32_t b1) {
    asm volatile(
        "mma.sync.aligned.m16n8k16.row.col.f32.f16.f16.f32 "
        "{%0,%1,%2,%3}, {%4,%5,%6,%7}, {%8,%9}, {%0,%1,%2,%3};"
        : "+f"(d[0]), "+f"(d[1]), "+f"(d[2]), "+f"(d[3])
        : "r"(a[0]), "r"(a[1]), "r"(a[2]), "r"(a[3]), "r"(b0), "r"(b1));
}
__device__ __forceinline__ void cp16(uint32_t saddr, const void* g) {
    asm volatile("cp.async.cg.shared.global [%0], [%1], 16;\n" :: "r"(saddr), "l"(g));
}
__device__ __forceinline__ uint32_t smem_u32(const void* p) {
    uint32_t a;
    asm("{ .reg .u64 t; cvta.to.shared.u64 t, %1; cvt.u32.u64 %0, t; }" : "=r"(a) : "l"(p));
    return a;
}
__device__ __forceinline__ void ldsm4(uint32_t r[4], uint32_t saddr) {
    asm volatile("ldmatrix.sync.aligned.m8n8.x4.shared.b16 {%0,%1,%2,%3}, [%4];"
        : "=r"(r[0]), "=r"(r[1]), "=r"(r[2]), "=r"(r[3]) : "r"(saddr));
}
__device__ __forceinline__ uint32_t h2u(__half2 h) { return *reinterpret_cast<uint32_t*>(&h); }
__device__ __forceinline__ float sigm(float x)  { return 1.f / (1.f + __expf(-x)); }
__device__ __forceinline__ float tanhq(float x) { return 1.f - 2.f / (1.f + __expf(2.f * x)); }

// ---------------- conversions ----------------
__global__ void round_f16(const float* __restrict__ in, __half* __restrict__ out, int n4) {
    int i = blockIdx.x * blockDim.x + threadIdx.x;
    if (i < n4) {
        float4 v = ((const float4*)in)[i];
        *(__half2*)(out + (size_t)i * 4)     = __floats2half2_rn(v.x, v.y);
        *(__half2*)(out + (size_t)i * 4 + 2) = __floats2half2_rn(v.z, v.w);
    }
}
__global__ void cvt_x(const float* __restrict__ in, __half* __restrict__ out, int n8) {
    const int stride = gridDim.x * blockDim.x;
    for (int i = blockIdx.x * blockDim.x + threadIdx.x; i < n8; i += stride) {
        float4 a = ((const float4*)in)[(size_t)2 * i];
        float4 b = ((const float4*)in)[(size_t)2 * i + 1];
        uint4 o;
        o.x = h2u(__floats2half2_rn(a.x, a.y));
        o.y = h2u(__floats2half2_rn(a.z, a.w));
        o.z = h2u(__floats2half2_rn(b.x, b.y));
        o.w = h2u(__floats2half2_rn(b.z, b.w));
        ((uint4*)out)[i] = o;
    }
}

// ---------------- GEMM fp16 (all 4 feed-forward GEMMs) — R10-proven ----------
template<bool THRESH, bool OUT16>
__global__ void __launch_bounds__(256, 2)
gemm_h(const __half* __restrict__ Ag, const __half* __restrict__ Bg,
       const float* __restrict__ bias, void* __restrict__ Cgv,
       int M, int N, int K, int ntiles, int tn)
{
    extern __shared__ __half smh[];
    constexpr int AS = 128 * LDH;
    constexpr int SS = 2 * AS;
    const int tid  = threadIdx.x;
    const int lane = tid & 31, warp = tid >> 5;
    const int wr = warp >> 1, wc = warp & 1;
    const int grp = lane >> 2, tig = lane & 3;
    const int sel = lane >> 3, rw = lane & 7;
    const int NT = K >> 5;
    const uint32_t smb = smem_u32(smh);

    int lr[2], lk[2];
#pragma unroll
    for (int i = 0; i < 2; i++) { int l = tid + i * 256; lr[i] = l >> 2; lk[i] = (l & 3) << 3; }

    uint32_t adA[2], adB[4];
#pragma unroll
    for (int mi = 0; mi < 2; mi++) {
        const int row = wr * 32 + mi * 16 + ((sel & 1) << 3) + rw;
        adA[mi] = smb + (uint32_t)(row * LDH + ((sel >> 1) << 3)) * 2u;
    }
#pragma unroll
    for (int p = 0; p < 4; p++) {
        const int row = wc * 64 + p * 16 + ((sel & 1) << 3) + rw;
        adB[p] = smb + (uint32_t)(AS + row * LDH + ((sel >> 1) << 3)) * 2u;
    }

    for (int tile = blockIdx.x; tile < ntiles; tile += gridDim.x) {
        const int bm = (tile / tn) << 7;
        const int bn = (tile % tn) << 7;
        const __half* Ab = Ag + (size_t)bm * K;
        const __half* Bb = Bg + (size_t)bn * K;

        auto issue = [&](int kt) {
            const int st = kt & 3;
            const int go = kt << 5;
#pragma unroll
            for (int i = 0; i < 2; i++) {
                uint32_t sa = smb + (uint32_t)(st * SS + lr[i] * LDH + lk[i]) * 2u;
                cp16(sa,           Ab + (size_t)lr[i] * K + go + lk[i]);
                cp16(sa + AS * 2u, Bb + (size_t)lr[i] * K + go + lk[i]);
            }
            asm volatile("cp.async.commit_group;\n");
        };

        float acc[2][8][4];
#pragma unroll
        for (int a = 0; a < 2; a++)
#pragma unroll
            for (int b = 0; b < 8; b++)
#pragma unroll
                for (int c = 0; c < 4; c++) acc[a][b][c] = 0.f;

        issue(0); issue(1); issue(2);

        for (int kt = 0; kt < NT; kt++) {
            const int rem = NT - 1 - kt;
            if (rem >= 2)      asm volatile("cp.async.wait_group 2;\n");
            else if (rem == 1) asm volatile("cp.async.wait_group 1;\n");
            else               asm volatile("cp.async.wait_group 0;\n");
            __syncthreads();
            if (kt + 3 < NT) issue(kt + 3);

            const uint32_t stoff = (uint32_t)((kt & 3) * SS) * 2u;
#pragma unroll
            for (int ks = 0; ks < 2; ks++) {
                const uint32_t koff = stoff + (uint32_t)(ks * 16) * 2u;
                uint32_t af[2][4], bq[4][4];
#pragma unroll
                for (int mi = 0; mi < 2; mi++) ldsm4(af[mi], adA[mi] + koff);
#pragma unroll
                for (int p = 0; p < 4; p++) ldsm4(bq[p], adB[p] + koff);
#pragma unroll
                for (int mi = 0; mi < 2; mi++)
#pragma unroll
                    for (int p = 0; p < 4; p++) {
                        mma_f16(acc[mi][2 * p],     af[mi], bq[p][0], bq[p][2]);
                        mma_f16(acc[mi][2 * p + 1], af[mi], bq[p][1], bq[p][3]);
                    }
            }
        }
        __syncthreads();

#pragma unroll
        for (int mi = 0; mi < 2; mi++) {
            const int r0 = bm + wr * 32 + mi * 16 + grp;
#pragma unroll
            for (int ni = 0; ni < 8; ni++) {
                const int c0 = bn + wc * 64 + ni * 8 + tig * 2;
                const float b0 = bias[c0], b1 = bias[c0 + 1];
                float v00 = acc[mi][ni][0] + b0, v01 = acc[mi][ni][1] + b1;
                float v10 = acc[mi][ni][2] + b0, v11 = acc[mi][ni][3] + b1;
                if (THRESH) {
                    v00 = (v00 > kThr) ? v00 : 0.f;  v01 = (v01 > kThr) ? v01 : 0.f;
                    v10 = (v10 > kThr) ? v10 : 0.f;  v11 = (v11 > kThr) ? v11 : 0.f;
                }
                if (OUT16) {
                    __half* Cg = (__half*)Cgv;
                    *(__half2*)&Cg[(size_t)r0 * N + c0]       = __floats2half2_rn(v00, v01);
                    *(__half2*)&Cg[(size_t)(r0 + 8) * N + c0] = __floats2half2_rn(v10, v11);
                } else {
                    float* Cg = (float*)Cgv;
                    *(float2*)&Cg[(size_t)r0 * N + c0]       = make_float2(v00, v01);
                    *(float2*)&Cg[(size_t)(r0 + 8) * N + c0] = make_float2(v10, v11);
                }
            }
        }
    }
}

// ---------------- per-mt group barrier (32 CTAs per group, 8 groups) ----------
__device__ __forceinline__ void group_barrier(int mt) {
    __syncthreads();
    if (threadIdx.x == 0) {
        unsigned gen = *((volatile unsigned*)&g_gen[mt][0]);
        __threadfence();
        if (atomicAdd(&g_cnt[mt][0], 1u) == 31u) {
            atomicExch(&g_cnt[mt][0], 0u);
            __threadfence();
            atomicAdd(&g_gen[mt][0], 1u);
        } else {
            while (*((volatile unsigned*)&g_gen[mt][0]) == gen) { __nanosleep(32); }
            __threadfence();
        }
    }
    __syncthreads();
}

// ---------------- persistent fused GRU: 256 CTAs, 2 CTAs/SM ------------------
// blockIdx = mt*32 + jc.  CTA owns batch rows [mt*128,+128) x gate cols
// [jc*16,+16).  Resident w_hh slice = 48 rows (r/z/n x 16 cols) x 512 -> 50KB;
// 105KB smem/CTA total => 2 CTAs/SM, 16 warps/SM (double R15's occupancy).
__global__ void __launch_bounds__(256, 2)
gru_persistent(const __half* __restrict__ gi, const float* __restrict__ w_hh,
               const float* __restrict__ b_hh,
               __half* __restrict__ hA, __half* __restrict__ hB)
{
    extern __shared__ __half smg[];
    __half* ws = smg;                          // [48][WS_LDH]
    __half* ht = smg + 48 * WS_LDH;            // 3 stages x [128][HT_LDH]
    constexpr int HTS = 128 * HT_LDH;

    const int tid  = threadIdx.x;
    const int lane = tid & 31, warp = tid >> 5;
    const int grp = lane >> 2, tig = lane & 3;
    const int sel = lane >> 3, rw = lane & 7;
    const int mt = blockIdx.x >> 5;            // 0..7
    const int jc = blockIdx.x & 31;            // 0..31
    const int m0 = mt * 128, j0 = jc * 16;

    // preload + convert resident w_hh slice: ws row (g*16+c) <- w_hh row (g*512 + j0 + c)
    for (int i4 = tid; i4 < 48 * 128; i4 += 256) {
        const int row = i4 >> 7, k4 = (i4 & 127) << 2;
        const int g = row >> 4, c = row & 15;
        float4 v = *(const float4*)(w_hh + (size_t)(g * kD + j0 + c) * kD + k4);
        *(__half2*)(ws + row * WS_LDH + k4)     = __floats2half2_rn(v.x, v.y);
        *(__half2*)(ws + row * WS_LDH + k4 + 2) = __floats2half2_rn(v.z, v.w);
    }

    // b_hh in regs: ni 0..5 -> gate g = ni>>1, col j0 + (ni&1)*8 + tig*2
    float bhh0[6], bhh1[6];
#pragma unroll
    for (int ni = 0; ni < 6; ni++) {
        const int g = ni >> 1, j = j0 + (ni & 1) * 8 + tig * 2;
        bhh0[ni] = b_hh[g * kD + j];
        bhh1[ni] = b_hh[g * kD + j + 1];
    }
    __syncthreads();

    // h-tile cp.async mapping: 128 rows x 8 chunks of 16B (BK=64 halves)
    int lr[4], lk[4];
#pragma unroll
    for (int i = 0; i < 4; i++) { int l = tid + i * 256; lr[i] = l >> 3; lk[i] = (l & 7) << 3; }
    const uint32_t smb_ht = smem_u32(ht);
    const uint32_t smb_ws = smem_u32(ws);

    uint32_t adA, adB[3];
    {
        const int row = warp * 16 + ((sel & 1) << 3) + rw;
        adA = smb_ht + (uint32_t)(row * HT_LDH + ((sel >> 1) << 3)) * 2u;
    }
#pragma unroll
    for (int p = 0; p < 3; p++) {              // bq[p] covers ws rows p*16..+16 (gate p)
        const int row = p * 16 + ((sel & 1) << 3) + rw;
        adB[p] = smb_ws + (uint32_t)(row * WS_LDH + ((sel >> 1) << 3)) * 2u;
    }

    for (int t = 0; t < kL; t++) {
        __half* src = (t & 1) ? hA : hB;
        __half* dst = (t & 1) ? hB : hA;

        float acc[6][4];                       // acc[2g+q]: gate g, col-half q
#pragma unroll
        for (int a = 0; a < 6; a++)
#pragma unroll
            for (int c = 0; c < 4; c++) acc[a][c] = 0.f;

        if (t > 0) {
            const __half* Ab = src + (size_t)m0 * kD;
            auto issue = [&](int kt) {        // kt in 0..7, BK=64 halves
                const int st = kt % 3;
                const int go = kt << 6;
#pragma unroll
                for (int i = 0; i < 4; i++) {
                    uint32_t sa = smb_ht + (uint32_t)(st * HTS + lr[i] * HT_LDH + lk[i]) * 2u;
                    cp16(sa, Ab + (size_t)lr[i] * kD + go + lk[i]);
                }
                asm volatile("cp.async.commit_group;\n");
            };
            issue(0); issue(1);

            for (int kt = 0; kt < 8; kt++) {
                if (kt + 1 < 8) asm volatile("cp.async.wait_group 1;\n");
                else            asm volatile("cp.async.wait_group 0;\n");
                __syncthreads();
                if (kt + 2 < 8) issue(kt + 2);

                const uint32_t stoff = (uint32_t)((kt % 3) * HTS) * 2u;
                const uint32_t kbyte = (uint32_t)(kt << 6) * 2u;
#pragma unroll
                for (int ks = 0; ks < 4; ks++) {   // four k16 steps
                    const uint32_t ko = (uint32_t)(ks * 16) * 2u;
                    uint32_t af[4], bq[3][4];
                    ldsm4(af, adA + stoff + ko);
#pragma unroll
                    for (int p = 0; p < 3; p++) ldsm4(bq[p], adB[p] + kbyte + ko);
#pragma unroll
                    for (int p = 0; p < 3; p++) {
                        mma_f16(acc[2 * p],     af, bq[p][0], bq[p][2]);
                        mma_f16(acc[2 * p + 1], af, bq[p][1], bq[p][3]);
                    }
                }
            }
            __syncthreads();
        }

        // fused gate update: acc[q]=gh_r, acc[q+2]=gh_z, acc[q+4]=gh_n (q = col-half)
#pragma unroll
        for (int q = 0; q < 2; q++) {
#pragma unroll
            for (int s = 0; s < 2; s++) {
                const int b  = m0 + warp * 16 + grp + s * 8;
                const int jj = j0 + q * 8 + tig * 2;
                const __half* gib = gi + ((size_t)b * kL + t) * (3 * kD);
                const float2 gr = __half22float2(*(const __half2*)(gib + jj));
                const float2 gz = __half22float2(*(const __half2*)(gib + kD + jj));
                const float2 gn = __half22float2(*(const __half2*)(gib + 2 * kD + jj));
                float2 hp = make_float2(0.f, 0.f);
                if (t > 0) hp = __half22float2(*(const __half2*)(src + (size_t)b * kD + jj));
                const float r0 = sigm(gr.x + acc[q][2 * s]     + bhh0[q]);
                const float r1 = sigm(gr.y + acc[q][2 * s + 1] + bhh1[q]);
                const float z0 = sigm(gz.x + acc[q + 2][2 * s]     + bhh0[q + 2]);
                const float z1 = sigm(gz.y + acc[q + 2][2 * s + 1] + bhh1[q + 2]);
                const float n0 = tanhq(gn.x + r0 * (acc[q + 4][2 * s]     + bhh0[q + 4]));
                const float n1 = tanhq(gn.y + r1 * (acc[q + 4][2 * s + 1] + bhh1[q + 4]));
                const float h0 = (1.f - z0) * n0 + z0 * hp.x;
                const float h1 = (1.f - z1) * n1 + z1 * hp.y;
                *(__half2*)(dst + (size_t)b * kD + jj) = __floats2half2_rn(h0, h1);
            }
        }
        if (t < kL - 1) group_barrier(mt);
    }
}

// ---------------- host ----------------
extern "C" void kernel_launch(void* const* d_in, const int* in_sizes, int n_in,
                              void* d_out, int out_size)
{
    (void)in_sizes; (void)n_in; (void)out_size;
    const float* x     = (const float*)d_in[0];
    const float* w1    = (const float*)d_in[1];
    const float* b1    = (const float*)d_in[2];
    const float* w2    = (const float*)d_in[3];
    const float* b2    = (const float*)d_in[4];
    const float* w_ih  = (const float*)d_in[5];
    const float* w_hh  = (const float*)d_in[6];
    const float* b_ih  = (const float*)d_in[7];
    const float* b_hh  = (const float*)d_in[8];
    const float* lin_w = (const float*)d_in[9];
    const float* lin_b = (const float*)d_in[10];
    float* out = (float*)d_out;

    __half *xh, *h1, *h2, *gi, *hA, *hB, *rw1h, *rw2h, *rwihh, *rlinh;
    cudaGetSymbolAddress((void**)&xh,    g_xh);
    cudaGetSymbolAddress((void**)&h1,    g_h1);
    cudaGetSymbolAddress((void**)&h2,    g_h2);
    cudaGetSymbolAddress((void**)&gi,    g_gi);
    cudaGetSymbolAddress((void**)&hA,    g_hA);
    cudaGetSymbolAddress((void**)&hB,    g_hB);
    cudaGetSymbolAddress((void**)&rw1h,  g_rw1h);
    cudaGetSymbolAddress((void**)&rw2h,  g_rw2h);
    cudaGetSymbolAddress((void**)&rwihh, g_rwihh);
    cudaGetSymbolAddress((void**)&rlinh, g_rlinh);

    constexpr int H16_SMEM  = 4 * 2 * 128 * LDH * 2;                    // 81920
    constexpr int GRU_SMEM  = (48 * WS_LDH + 3 * 128 * HT_LDH) * 2;     // 105216
    cudaFuncSetAttribute(gemm_h<true,  true >, cudaFuncAttributeMaxDynamicSharedMemorySize, H16_SMEM);
    cudaFuncSetAttribute(gemm_h<false, true >, cudaFuncAttributeMaxDynamicSharedMemorySize, H16_SMEM);
    cudaFuncSetAttribute(gemm_h<false, false>, cudaFuncAttributeMaxDynamicSharedMemorySize, H16_SMEM);
    cudaFuncSetAttribute(gru_persistent,       cudaFuncAttributeMaxDynamicSharedMemorySize, GRU_SMEM);

    const int tm = kM / 128;   // 208

    // 1: x -> fp16 (grid-stride streaming convert)
    cvt_x<<<4096, 256>>>(x, xh, kM * kA / 8);
    // 2-3: weight converts (keeps conv1 at ncu's captured slot #4)
    round_f16<<<(kC1 * kA / 4 + 255) / 256, 256>>>(w1, rw1h, kC1 * kA / 4);
    round_f16<<<(kD * kC1 / 4 + 255) / 256, 256>>>(w2, rw2h, kD * kC1 / 4);

    // 4: conv1 [26624,8192] x [256,8192]^T (fp16, thresh, fp16 out)
    gemm_h<true, true ><<<tm * 2, 256, H16_SMEM>>>(xh, rw1h, b1, h1, kM, kC1, kA, tm * 2, 2);

    // 5: w_ih convert
    round_f16<<<(3 * kD * kD / 4 + 255) / 256, 256>>>(w_ih, rwihh, 3 * kD * kD / 4);
    // 6: conv2 [26624,256] x [512,256]^T (fp16, thresh, fp16 out)
    gemm_h<true, true ><<<tm * 4, 256, H16_SMEM>>>(h1, rw2h, b2, h2, kM, kD, kC1, tm * 4, 4);
    // 7: gi [26624,512] x [1536,512]^T (fp16 in/out)
    gemm_h<false, true ><<<tm * 12, 256, H16_SMEM>>>(h2, rwihh, b_ih, gi, kM, 3 * kD, kD, tm * 12, 12);
    // 8: lin_w convert
    round_f16<<<(kE * kD / 4 + 255) / 256, 256>>>(lin_w, rlinh, kE * kD / 4);
    // 9: fused persistent GRU (256 CTAs, 2/SM; kL even -> final h lands in hB)
    gru_persistent<<<256, 256, GRU_SMEM>>>(gi, w_hh, b_hh, hA, hB);
    // 10: out = h_last @ lin_w^T + lin_b (fp16 in, f32 out)
    gemm_h<false, false><<<8 * 8, 256, H16_SMEM>>>(hB, rlinh, lin_b, out, kB, kE, kD, 8 * 8, 8);
}